// round 12
// baseline (speedup 1.0000x reference)
#include <cuda_runtime.h>
#include <cuda_bf16.h>

#define IMG_H 4096
#define IMG_W 4096
#define OUT_H 4097
#define OUT_W 4097
#define TILE  32
#define HIST  35   // TILE + 3
#define INW   37   // HIST + 2 (sobel halo)
#define INP   38   // padded input row stride (words)
#define HP    37   // packed (mag|idx) row stride (odd)

__device__ __forceinline__ float4 f4add(float4 a, float4 b) {
    return make_float4(a.x + b.x, a.y + b.y, a.z + b.z, a.w + b.w);
}

__global__ __launch_bounds__(256, 5)
void sift_fused_kernel(const float* __restrict__ x, float* __restrict__ out)
{
    // rs: [chan-group][hist row][x] -> lane(x) contiguous float4
    __shared__ float4       s_rs[2][HIST][TILE];  // 35840 B (aliased as input tile)
    __shared__ unsigned int s_pk[HIST][HP];       //  5180 B packed mag|idx
    // total 41020 B -> 5 CTAs/SM

    float* s_in = (float*)s_rs;   // [INW][INP] = 5624 B, dead after stage 2

    const int X0   = blockIdx.x * TILE;
    const int Y0   = blockIdx.y * TILE;
    const int tid  = threadIdx.x;
    const int lane = tid & 31;
    const int wrow = tid >> 5;    // 0..7

    const bool interior =
        blockIdx.x >= 1 && blockIdx.x <= 126 &&
        blockIdx.y >= 1 && blockIdx.y <= 126;

    // ---- Stage 1: load input tile (origin Y0-3, X0-3) ----
    if (interior) {
        const float* src = x + (size_t)(Y0 - 3) * IMG_W + (X0 - 3);
        #pragma unroll
        for (int it = 0; it < 5; ++it) {
            int r = wrow + 8 * it;
            if (r < INW) {
                const float* row = src + (size_t)r * IMG_W;
                s_in[r * INP + lane] = row[lane];
                if (lane < INW - 32)
                    s_in[r * INP + 32 + lane] = row[32 + lane];
            }
        }
    } else {
        #pragma unroll
        for (int it = 0; it < 5; ++it) {
            int r = wrow + 8 * it;
            if (r < INW) {
                int  gy    = Y0 - 3 + r;
                bool rowok = (gy >= 0) && (gy < IMG_H);
                int  gx    = X0 - 3 + lane;
                float v = 0.0f;
                if (rowok && gx >= 0 && gx < IMG_W)
                    v = x[(size_t)gy * IMG_W + gx];
                s_in[r * INP + lane] = v;
                if (lane < INW - 32) {
                    int gx2 = gx + 32;
                    float v2 = 0.0f;
                    if (rowok && gx2 >= 0 && gx2 < IMG_W)
                        v2 = x[(size_t)gy * IMG_W + gx2];
                    s_in[r * INP + 32 + lane] = v2;
                }
            }
        }
    }
    __syncthreads();

    // ---- Stage 2: flat per-pixel Sobel + octant bin + packed store ----
    #pragma unroll
    for (int it = 0; it < 5; ++it) {
        int e = tid + 256 * it;
        if (e < HIST * HIST) {
            int h = e / HIST, w = e % HIST;
            const float* c = s_in + h * INP + w;
            float a00 = c[0],       a01 = c[1],           a02 = c[2];
            float a10 = c[INP],                            a12 = c[INP + 2];
            float a20 = c[2*INP],   a21 = c[2*INP + 1],   a22 = c[2*INP + 2];

            float dx = (a02 - a00) + 2.0f * (a12 - a10) + (a22 - a20);
            float dy = (a20 - a00) + 2.0f * (a21 - a01) + (a22 - a02);

            // octant bin == argmax over the 8 orientation cosines
            unsigned int sx = __float_as_uint(dx) >> 31;
            unsigned int sy = __float_as_uint(dy) >> 31;
            unsigned int tb = (fabsf(dy) > fabsf(dx)) ? 1u : 0u;
            unsigned int ex = sx ^ sy;
            unsigned int bi = (sy << 2) | (ex << 1) | (ex ^ tb);

            float m2  = fmaf(dx, dx, dy * dy);
            float mag = m2 * rsqrtf(fmaxf(m2, 1e-35f));

            unsigned int bits = (__float_as_uint(mag) & 0xFFFFFFF8u) | bi;

            if (!interior) {
                int gy = Y0 - 2 + h;
                int gx = X0 - 2 + w;
                if (!(gy >= 0 && gy < IMG_H && gx >= 0 && gx < IMG_W)) bits = 0u;
            }
            s_pk[h][w] = bits;
        }
    }
    __syncthreads();

    // ---- Stage 3: horizontal 4-tap row sums with one-hot scatter ----
    #pragma unroll
    for (int it = 0; it < 5; ++it) {
        int e = tid + 256 * it;
        if (e < HIST * TILE) {
            int h  = e >> 5;
            int ox = e & 31;
            float a0 = 0.f, a1 = 0.f, a2 = 0.f, a3 = 0.f;
            float a4 = 0.f, a5 = 0.f, a6 = 0.f, a7 = 0.f;
            #pragma unroll
            for (int k = 0; k < 4; k++) {
                unsigned int u = s_pk[h][ox + k];
                unsigned int i = u & 7u;
                float m = __uint_as_float(u);   // idx bits: <=2^-21 rel noise
                if (i == 0u) a0 += m;
                if (i == 1u) a1 += m;
                if (i == 2u) a2 += m;
                if (i == 3u) a3 += m;
                if (i == 4u) a4 += m;
                if (i == 5u) a5 += m;
                if (i == 6u) a6 += m;
                if (i == 7u) a7 += m;
            }
            s_rs[0][h][ox] = make_float4(a0, a1, a2, a3);
            s_rs[1][h][ox] = make_float4(a4, a5, a6, a7);
        }
    }
    __syncthreads();

    // ---- Stage 4: vertical 4-tap via streamed pair tree, two half-passes ----
    // o_r = p_r + p_{r+2},  p_i = row_i + row_{i+1}; 7 loads per half.
    const int    gx    = X0 + lane;
    const size_t plane = (size_t)OUT_H * OUT_W;
    const int    oy0   = wrow * 4;          // 4 consecutive output rows
    const bool   xok   = (gx < OUT_W);

    #pragma unroll
    for (int half = 0; half < 2; ++half) {
        const float4* col = &s_rs[half][0][lane];
        float* op = out + (size_t)(4 * half) * plane;

        float4 rA = col[(oy0    ) * TILE];
        float4 rB = col[(oy0 + 1) * TILE];
        float4 p0 = f4add(rA, rB);
        rA = col[(oy0 + 2) * TILE];
        float4 p1 = f4add(rB, rA);
        rB = col[(oy0 + 3) * TILE];
        float4 p2 = f4add(rA, rB);

        #define EMIT(OV, R) do {                                          \
            int gy = Y0 + oy0 + (R);                                      \
            if (xok && gy < OUT_H) {                                      \
                float4 _o = (OV);                                         \
                size_t base = (size_t)gy * OUT_W + gx;                    \
                op[base]             = _o.x;                              \
                op[plane + base]     = _o.y;                              \
                op[2 * plane + base] = _o.z;                              \
                op[3 * plane + base] = _o.w;                              \
            }                                                             \
        } while (0)

        EMIT(f4add(p0, p2), 0);
        rA = col[(oy0 + 4) * TILE];
        float4 p3 = f4add(rB, rA);
        EMIT(f4add(p1, p3), 1);
        rB = col[(oy0 + 5) * TILE];
        float4 p4 = f4add(rA, rB);
        EMIT(f4add(p2, p4), 2);
        rA = col[(oy0 + 6) * TILE];
        float4 p5 = f4add(rB, rA);
        EMIT(f4add(p3, p5), 3);
        #undef EMIT
    }
}

extern "C" void kernel_launch(void* const* d_in, const int* in_sizes, int n_in,
                              void* d_out, int out_size)
{
    const float* x   = (const float*)d_in[0];
    float*       out = (float*)d_out;
    dim3 grid((OUT_W + TILE - 1) / TILE, (OUT_H + TILE - 1) / TILE);  // 129 x 129
    sift_fused_kernel<<<grid, 256>>>(x, out);
}